// round 8
// baseline (speedup 1.0000x reference)
#include <cuda_runtime.h>
#include <cuda_bf16.h>
#include <cuda_fp16.h>
#include <cuda_fp8.h>
#include <cstdint>
#include <math.h>

// Problem constants
#define B_   2
#define S_   2048
#define HID_ 2048
#define NH_  32
#define NKV_ 8
#define HD_  64
#define GROUP_ 4
#define M_TOT (B_ * S_)          // 4096
#define NKVD (NKV_ * HD_)        // 512
#define NQKV (HID_ + 2 * NKVD)   // 3072

#define FOLD18 3.814697265625e-06f   // 2^-18

// ---------------------------------------------------------------------------
// Scratch (__device__ globals; no cudaMalloc allowed)
// ---------------------------------------------------------------------------
__device__ float g_QKV[(size_t)M_TOT * NQKV];

// A-side operands (fp16 hi + fp8 direct + fp8 lo*2^12)
__device__ __half  g_h16[(size_t)M_TOT * HID_];
__device__ uint8_t g_hq[(size_t)M_TOT * HID_], g_hlq[(size_t)M_TOT * HID_];
__device__ __half  g_c16[(size_t)M_TOT * HID_];
__device__ uint8_t g_cq[(size_t)M_TOT * HID_], g_clq[(size_t)M_TOT * HID_];
// B-side operands (fp16 hi + fp8*2^6 + fp8 lo*2^18)
__device__ __half  g_wc16[(size_t)NQKV * HID_];
__device__ uint8_t g_wcq[(size_t)NQKV * HID_], g_wclq[(size_t)NQKV * HID_];
__device__ __half  g_wo16[(size_t)HID_ * HID_];
__device__ uint8_t g_woq[(size_t)HID_ * HID_], g_wolq[(size_t)HID_ * HID_];
// Attention operands (bf16 hi/lo, unchanged)
__device__ __nv_bfloat16 g_qh[(size_t)M_TOT * HID_], g_ql[(size_t)M_TOT * HID_];
__device__ __nv_bfloat16 g_kh[(size_t)M_TOT * NKVD], g_kl[(size_t)M_TOT * NKVD];
__device__ __nv_bfloat16 g_vh[(size_t)M_TOT * NKVD], g_vl[(size_t)M_TOT * NKVD];

__device__ float g_rsin[S_ * 32], g_rcos[S_ * 32];

// ---------------------------------------------------------------------------
// Helpers
// ---------------------------------------------------------------------------
__device__ __forceinline__ uint32_t smem_u32(const void* p) {
    uint32_t a;
    asm("{ .reg .u64 t; cvta.to.shared.u64 t, %1; cvt.u32.u64 %0, t; }" : "=r"(a) : "l"(p));
    return a;
}
__device__ __forceinline__ void cp16(uint32_t dst, const void* src) {
    asm volatile("cp.async.cg.shared.global [%0], [%1], 16;" :: "r"(dst), "l"(src));
}
__device__ __forceinline__ void cp_commit() { asm volatile("cp.async.commit_group;"); }
__device__ __forceinline__ void cp_wait1() { asm volatile("cp.async.wait_group 1;"); }
__device__ __forceinline__ void cp_wait0() { asm volatile("cp.async.wait_group 0;"); }
__device__ __forceinline__ void ldsm4(uint32_t* r, uint32_t addr) {
    asm volatile("ldmatrix.sync.aligned.m8n8.x4.shared.b16 {%0,%1,%2,%3}, [%4];"
        : "=r"(r[0]), "=r"(r[1]), "=r"(r[2]), "=r"(r[3]) : "r"(addr));
}
__device__ __forceinline__ void ldsm4t(uint32_t* r, uint32_t addr) {
    asm volatile("ldmatrix.sync.aligned.m8n8.x4.trans.shared.b16 {%0,%1,%2,%3}, [%4];"
        : "=r"(r[0]), "=r"(r[1]), "=r"(r[2]), "=r"(r[3]) : "r"(addr));
}
__device__ __forceinline__ void mma_bf16(float* c, const uint32_t* a, const uint32_t* b) {
    asm volatile(
        "mma.sync.aligned.m16n8k16.row.col.f32.bf16.bf16.f32 "
        "{%0,%1,%2,%3}, {%4,%5,%6,%7}, {%8,%9}, {%0,%1,%2,%3};"
        : "+f"(c[0]), "+f"(c[1]), "+f"(c[2]), "+f"(c[3])
        : "r"(a[0]), "r"(a[1]), "r"(a[2]), "r"(a[3]), "r"(b[0]), "r"(b[1]));
}
__device__ __forceinline__ void mma_f16(float* c, const uint32_t* a, const uint32_t* b) {
    asm volatile(
        "mma.sync.aligned.m16n8k16.row.col.f32.f16.f16.f32 "
        "{%0,%1,%2,%3}, {%4,%5,%6,%7}, {%8,%9}, {%0,%1,%2,%3};"
        : "+f"(c[0]), "+f"(c[1]), "+f"(c[2]), "+f"(c[3])
        : "r"(a[0]), "r"(a[1]), "r"(a[2]), "r"(a[3]), "r"(b[0]), "r"(b[1]));
}
__device__ __forceinline__ void mma_fp8(float* c, const uint32_t* a, const uint32_t* b) {
    asm volatile(
        "mma.sync.aligned.m16n8k32.row.col.f32.e4m3.e4m3.f32 "
        "{%0,%1,%2,%3}, {%4,%5,%6,%7}, {%8,%9}, {%0,%1,%2,%3};"
        : "+f"(c[0]), "+f"(c[1]), "+f"(c[2]), "+f"(c[3])
        : "r"(a[0]), "r"(a[1]), "r"(a[2]), "r"(a[3]), "r"(b[0]), "r"(b[1]));
}
__device__ __forceinline__ uint32_t pack_bf16(float x, float y) {
    __nv_bfloat162 h = __floats2bfloat162_rn(x, y);
    return *(uint32_t*)&h;
}
__device__ __forceinline__ uint8_t to_e4m3(float x) {
    return (uint8_t)__nv_cvt_float_to_fp8(x, __NV_SATFINITE, __NV_E4M3);
}

// ---------------------------------------------------------------------------
// Split kernels
// ---------------------------------------------------------------------------
// A-side (sigma ~ 1): h16 = fp16(x), hq = e4m3(x), hlq = e4m3((x-h16)*2^12)
__global__ void split_a(const float* __restrict__ x, __half* __restrict__ h16,
                        uint8_t* __restrict__ hq, uint8_t* __restrict__ hlq, int n) {
    int i = blockIdx.x * blockDim.x + threadIdx.x;
    if (i < n) {
        float v = x[i];
        __half h = __float2half_rn(v);
        h16[i] = h;
        hq[i] = to_e4m3(v);
        hlq[i] = to_e4m3((v - __half2float(h)) * 4096.0f);
    }
}
// B-side (weights, sigma ~ 0.02): w16 = fp16(x), wq = e4m3(x*2^6), wlq = e4m3((x-w16)*2^18)
__global__ void split_b(const float* __restrict__ x, __half* __restrict__ w16,
                        uint8_t* __restrict__ wq, uint8_t* __restrict__ wlq, int n) {
    int i = blockIdx.x * blockDim.x + threadIdx.x;
    if (i < n) {
        float v = x[i];
        __half h = __float2half_rn(v);
        w16[i] = h;
        wq[i] = to_e4m3(v * 64.0f);
        wlq[i] = to_e4m3((v - __half2float(h)) * 262144.0f);
    }
}

// ---------------------------------------------------------------------------
// GEMM: fp16 hi-pass + fp8 cross-pass. C[M,N] = A[M,K]*B[N,K]^T.
// CTA 128x256x32, 512 thr (16 warps, warp 32x64), 3-stage cp.async.
// ---------------------------------------------------------------------------
#define BM 128
#define BN 256
#define BK 32
#define LDSS 40                  // fp16 row stride (elems)
#define LD8 48                   // fp8 row stride (bytes)
#define A16B (BM * LDSS * 2)     // 10240
#define A8B  (BM * LD8)          // 6144
#define B16B (BN * LDSS * 2)     // 20480
#define B8B  (BN * LD8)          // 12288
#define STGB (A16B + 2 * A8B + B16B + 2 * B8B)   // 67584
#define GSTG 3

__global__ void __launch_bounds__(512, 1) gemm_mma(
    const __half* __restrict__ A16, const uint8_t* __restrict__ Aq, const uint8_t* __restrict__ Alq,
    const __half* __restrict__ B16, const uint8_t* __restrict__ Bq, const uint8_t* __restrict__ Blq,
    float* __restrict__ C, int M, int N, int K)
{
    extern __shared__ char dyn[];

    const int tid = threadIdx.x;
    const int warp = tid >> 5, lane = tid & 31;
    const int wm = (warp >> 2) * 32;
    const int wn = (warp & 3) * 64;
    const int g = lane >> 2, t = lane & 3;
    const int l8 = lane & 7, half_ = (lane >> 3) & 1, kq = lane >> 4;
    const int m0 = blockIdx.y * BM, n0 = blockIdx.x * BN;

    const uint32_t sb = smem_u32(dyn);

    float acc[2][8][4];
#pragma unroll
    for (int i = 0; i < 2; i++)
#pragma unroll
        for (int j = 0; j < 8; j++)
#pragma unroll
            for (int x = 0; x < 4; x++) acc[i][j][x] = 0.f;

    const int nch = K / BK;

    auto issue = [&](int kc, int st) {
        uint32_t so = sb + (uint32_t)st * STGB;
        // A fp16: 128 rows x 64B = 512 cp16
        {
            int row = tid >> 2, q = tid & 3;
            cp16(so + (row * LDSS + q * 8) * 2,
                 A16 + (size_t)(m0 + row) * K + kc * BK + q * 8);
        }
        // B fp16: 256 rows x 64B = 1024 cp16
#pragma unroll
        for (int i = 0; i < 2; i++) {
            int idx = tid + i * 512;
            int row = idx >> 2, q = idx & 3;
            cp16(so + A16B + 2 * A8B + (row * LDSS + q * 8) * 2,
                 B16 + (size_t)(n0 + row) * K + kc * BK + q * 8);
        }
        // A fp8 (hq / lq): 128 rows x 32B = 256 cp16 each
        {
            int half_sel = tid >> 8;            // 0: Aq, 1: Alq
            int idx = tid & 255;
            int row = idx >> 1, q = idx & 1;
            const uint8_t* src = half_sel ? Alq : Aq;
            uint32_t off = half_sel ? (A16B + A8B) : A16B;
            cp16(so + off + row * LD8 + q * 16,
                 src + (size_t)(m0 + row) * K + kc * BK + q * 16);
        }
        // B fp8: 256 rows x 32B = 512 cp16 each
        {
            int row = tid >> 1, q = tid & 1;
            uint32_t boff = A16B + 2 * A8B + B16B + row * LD8 + q * 16;
            size_t gsrc = (size_t)(n0 + row) * K + kc * BK + q * 16;
            cp16(so + boff,       Bq + gsrc);
            cp16(so + boff + B8B, Blq + gsrc);
        }
        cp_commit();
    };

    issue(0, 0);
    if (nch > 1) issue(1, 1);

    for (int kc = 0; kc < nch; kc++) {
        if (kc + 1 < nch) cp_wait1(); else cp_wait0();
        __syncthreads();
        if (kc + 2 < nch) issue(kc + 2, (kc + 2) % GSTG);

        const uint32_t sa = sb + (uint32_t)(kc % GSTG) * STGB;
        const uint32_t A16o = sa;
        const uint32_t AHQo = sa + A16B;
        const uint32_t ALQo = sa + A16B + A8B;
        const uint32_t B16o = sa + A16B + 2 * A8B;
        const uint32_t BHQo = B16o + B16B;
        const uint32_t BLQo = BHQo + B8B;

        // --- fp16 hi pass ---
#pragma unroll
        for (int ks = 0; ks < 2; ks++) {
            const int kb = ks * 16 + kq * 8;
            uint32_t af[2][4];
#pragma unroll
            for (int mi = 0; mi < 2; mi++) {
                uint32_t ad = ((wm + mi * 16 + l8 + half_ * 8) * LDSS + kb) * 2;
                ldsm4(af[mi], A16o + ad);
            }
#pragma unroll
            for (int p = 0; p < 4; p++) {
                uint32_t bd = ((wn + p * 16 + l8 + half_ * 8) * LDSS + kb) * 2;
                uint32_t tb[4];
                ldsm4(tb, B16o + bd);
                uint32_t be0[2] = {tb[0], tb[2]}, be1[2] = {tb[1], tb[3]};
#pragma unroll
                for (int mi = 0; mi < 2; mi++) {
                    mma_f16(acc[mi][2 * p],     af[mi], be0);
                    mma_f16(acc[mi][2 * p + 1], af[mi], be1);
                }
            }
        }

        // --- fp8 cross pass (full k32 per mma) ---
        uint32_t ah8[2][4], al8[2][4];
#pragma unroll
        for (int mi = 0; mi < 2; mi++) {
            uint32_t ad = (wm + mi * 16 + l8 + half_ * 8) * LD8 + kq * 16;
            ldsm4(ah8[mi], AHQo + ad);
            ldsm4(al8[mi], ALQo + ad);
        }
#pragma unroll
        for (int p = 0; p < 4; p++) {
            uint32_t bd = (wn + p * 16 + l8 + half_ * 8) * LD8 + kq * 16;
            uint32_t tbh[4], tbl[4];
            ldsm4(tbh, BHQo + bd);
            ldsm4(tbl, BLQo + bd);
            uint32_t bh0[2] = {tbh[0], tbh[2]}, bh1[2] = {tbh[1], tbh[3]};
            uint32_t bl0[2] = {tbl[0], tbl[2]}, bl1[2] = {tbl[1], tbl[3]};
#pragma unroll
            for (int mi = 0; mi < 2; mi++) {
                float tmp[4] = {0.f, 0.f, 0.f, 0.f};
                mma_fp8(tmp, ah8[mi], bl0);     // Ah * Bl  (scale 2^18)
                mma_fp8(tmp, al8[mi], bh0);     // Al * Bh  (scale 2^18)
#pragma unroll
                for (int x = 0; x < 4; x++) acc[mi][2 * p][x] += tmp[x] * FOLD18;
                float tm2[4] = {0.f, 0.f, 0.f, 0.f};
                mma_fp8(tm2, ah8[mi], bl1);
                mma_fp8(tm2, al8[mi], bh1);
#pragma unroll
                for (int x = 0; x < 4; x++) acc[mi][2 * p + 1][x] += tm2[x] * FOLD18;
            }
        }
    }

#pragma unroll
    for (int mi = 0; mi < 2; mi++) {
        int r = m0 + wm + mi * 16 + g;
#pragma unroll
        for (int ni = 0; ni < 8; ni++) {
            int c = n0 + wn + ni * 8 + 2 * t;
            *(float2*)&C[(size_t)r * N + c] = make_float2(acc[mi][ni][0], acc[mi][ni][1]);
            *(float2*)&C[(size_t)(r + 8) * N + c] = make_float2(acc[mi][ni][2], acc[mi][ni][3]);
        }
    }
}

// ---------------------------------------------------------------------------
// RoPE: table + apply-and-split (fp32 strided in, bf16 hi/lo packed out)
// ---------------------------------------------------------------------------
__global__ void rope_table_kernel() {
    int i = blockIdx.x * blockDim.x + threadIdx.x;
    int s = i >> 5, f = i & 31;
    double inv_freq = exp(-(double)f / 32.0 * log(10000.0));
    double sd, cd;
    sincos((double)s * inv_freq, &sd, &cd);
    g_rsin[i] = (float)sd;
    g_rcos[i] = (float)cd;
}
__global__ void rope_split_kernel(const float* __restrict__ X,
                                  __nv_bfloat16* __restrict__ Xh,
                                  __nv_bfloat16* __restrict__ Xl,
                                  int nheads, int src_off) {
    int idx = blockIdx.x * blockDim.x + threadIdx.x;
    int i = idx & 31;
    int bh = idx >> 5;
    int h = bh % nheads;
    int bs = bh / nheads;
    int s = bs & (S_ - 1);
    float c = g_rcos[s * 32 + i], sn = g_rsin[s * 32 + i];
    size_t sbase = (size_t)bs * NQKV + src_off + h * HD_;
    size_t dbase = (size_t)bs * nheads * HD_ + (size_t)h * HD_;
    float x1 = X[sbase + i], x2 = X[sbase + i + 32];
    float y1 = x1 * c - x2 * sn;
    float y2 = x2 * c + x1 * sn;
    __nv_bfloat16 h1 = __float2bfloat16(y1);
    __nv_bfloat16 h2 = __float2bfloat16(y2);
    Xh[dbase + i] = h1;
    Xh[dbase + i + 32] = h2;
    Xl[dbase + i] = __float2bfloat16(y1 - __bfloat162float(h1));
    Xl[dbase + i + 32] = __float2bfloat16(y2 - __bfloat162float(h2));
}
__global__ void split_v_kernel(const float* __restrict__ X,
                               __nv_bfloat16* __restrict__ hi,
                               __nv_bfloat16* __restrict__ lo) {
    int idx = blockIdx.x * blockDim.x + threadIdx.x;
    int row = idx >> 9, col = idx & 511;
    float v = X[(size_t)row * NQKV + HID_ + NKVD + col];
    __nv_bfloat16 h = __float2bfloat16(v);
    hi[idx] = h;
    lo[idx] = __float2bfloat16(v - __bfloat162float(h));
}

// ---------------------------------------------------------------------------
// Tensor-core flash attention (bf16x3, causal), 3-stage cp.async pipeline,
// ldmatrix K + ldmatrix.trans V. Epilogue writes fp16/fp8 context for O-proj.
// grid=(S/128, NH, B), block=256.
// ---------------------------------------------------------------------------
#define LDK 72
#define KVT (64 * LDK)
#define FSTG 3

__global__ void __launch_bounds__(256, 1) flash_mma(
    const __nv_bfloat16* __restrict__ qh, const __nv_bfloat16* __restrict__ ql,
    const __nv_bfloat16* __restrict__ kh, const __nv_bfloat16* __restrict__ kl,
    const __nv_bfloat16* __restrict__ vh, const __nv_bfloat16* __restrict__ vl,
    __half* __restrict__ c16, uint8_t* __restrict__ cq, uint8_t* __restrict__ clq)
{
    extern __shared__ __nv_bfloat16 fdyn[];

    const int tid = threadIdx.x;
    const int w = tid >> 5, lane = tid & 31;
    const int g = lane >> 2, t = lane & 3;
    const int l8 = lane & 7, half_ = (lane >> 3) & 1, kq = lane >> 4;
    const int qt = blockIdx.x, h = blockIdx.y, b = blockIdx.z;
    const int kvh = h / GROUP_;
    const int row_base = qt * 128 + w * 16;
    const float SCALE = 0.125f;
    const uint32_t sb = smem_u32(fdyn);

    uint32_t aqh[4][4], aql[4][4];
    {
        const __nv_bfloat16* qb = qh + ((size_t)(b * S_ + row_base)) * HID_ + h * HD_;
        const __nv_bfloat16* qb2 = ql + ((size_t)(b * S_ + row_base)) * HID_ + h * HD_;
#pragma unroll
        for (int j = 0; j < 4; j++) {
            int k0 = j * 16 + 2 * t;
            aqh[j][0] = *(const uint32_t*)&qb[(size_t)g * HID_ + k0];
            aqh[j][1] = *(const uint32_t*)&qb[(size_t)(g + 8) * HID_ + k0];
            aqh[j][2] = *(const uint32_t*)&qb[(size_t)g * HID_ + k0 + 8];
            aqh[j][3] = *(const uint32_t*)&qb[(size_t)(g + 8) * HID_ + k0 + 8];
            aql[j][0] = *(const uint32_t*)&qb2[(size_t)g * HID_ + k0];
            aql[j][1] = *(const uint32_t*)&qb2[(size_t)(g + 8) * HID_ + k0];
            aql[j][2] = *(const uint32_t*)&qb2[(size_t)g * HID_ + k0 + 8];
            aql[j][3] = *(const uint32_t*)&qb2[(size_t)(g + 8) * HID_ + k0 + 8];
        }
    }

    float o[8][4];
#pragma unroll
    for (int i = 0; i < 8; i++)
#pragma unroll
        for (int j = 0; j < 4; j++) o[i][j] = 0.f;
    float m0 = -INFINITY, m1 = -INFINITY, l0 = 0.f, l1 = 0.f;

    const int ntiles = 2 * qt + 2;

    auto issue = [&](int kt, int st) {
        uint32_t so = sb + (uint32_t)st * 4 * KVT * 2;
#pragma unroll
        for (int i = 0; i < 2; i++) {
            int idx = tid + i * 256;
            int r = idx >> 3, q = idx & 7;
            size_t go = ((size_t)(b * S_ + kt * 64 + r)) * NKVD + kvh * HD_ + q * 8;
            uint32_t off = (r * LDK + q * 8) * 2;
            cp16(so + off,               kh + go);
            cp16(so + KVT * 2 + off,     kl + go);
            cp16(so + 2 * KVT * 2 + off, vh + go);
            cp16(so + 3 * KVT * 2 + off, vl + go);
        }
        cp_commit();
    };

    issue(0, 0);
    if (ntiles > 1) issue(1, 1);

    for (int kt = 0; kt < ntiles; kt++) {
        if (kt + 1 < ntiles) cp_wait1(); else cp_wait0();
        __syncthreads();
        if (kt + 2 < ntiles) issue(kt + 2, (kt + 2) % FSTG);

        const uint32_t sg = sb + (uint32_t)(kt % FSTG) * 4 * KVT * 2;
        const uint32_t sKh_ = sg, sKl_ = sg + KVT * 2;
        const uint32_t sVh_ = sg + 2 * KVT * 2, sVl_ = sg + 3 * KVT * 2;

        const bool skip = (kt * 64) > (row_base + 15);
        if (!skip) {
            float s[8][4];
#pragma unroll
            for (int i = 0; i < 8; i++)
#pragma unroll
                for (int j = 0; j < 4; j++) s[i][j] = 0.f;
#pragma unroll
            for (int j = 0; j < 4; j++) {
                const int kb = j * 16 + kq * 8;
#pragma unroll
                for (int kp = 0; kp < 4; kp++) {
                    uint32_t ad = ((kp * 16 + l8 + half_ * 8) * LDK + kb) * 2;
                    uint32_t th[4], tl[4];
                    ldsm4(th, sKh_ + ad);
                    ldsm4(tl, sKl_ + ad);
                    uint32_t be0[2] = {th[0], th[2]}, be1[2] = {th[1], th[3]};
                    uint32_t bl0[2] = {tl[0], tl[2]}, bl1[2] = {tl[1], tl[3]};
                    mma_bf16(s[2 * kp], aqh[j], be0);
                    mma_bf16(s[2 * kp], aqh[j], bl0);
                    mma_bf16(s[2 * kp], aql[j], be0);
                    mma_bf16(s[2 * kp + 1], aqh[j], be1);
                    mma_bf16(s[2 * kp + 1], aqh[j], bl1);
                    mma_bf16(s[2 * kp + 1], aql[j], be1);
                }
            }
            const int r0 = row_base + g, r1 = row_base + g + 8;
#pragma unroll
            for (int ni = 0; ni < 8; ni++) {
                int c0 = kt * 64 + ni * 8 + 2 * t;
                s[ni][0] *= SCALE; s[ni][1] *= SCALE; s[ni][2] *= SCALE; s[ni][3] *= SCALE;
                if ((kt * 64 + 63) > r0 || (kt * 64 + 63) > r1) {
                    if (c0 > r0)     s[ni][0] = -INFINITY;
                    if (c0 + 1 > r0) s[ni][1] = -INFINITY;
                    if (c0 > r1)     s[ni][2] = -INFINITY;
                    if (c0 + 1 > r1) s[ni][3] = -INFINITY;
                }
            }
            float mx0 = -INFINITY, mx1 = -INFINITY;
#pragma unroll
            for (int ni = 0; ni < 8; ni++) {
                mx0 = fmaxf(mx0, fmaxf(s[ni][0], s[ni][1]));
                mx1 = fmaxf(mx1, fmaxf(s[ni][2], s[ni][3]));
            }
            mx0 = fmaxf(mx0, __shfl_xor_sync(0xffffffff, mx0, 1));
            mx0 = fmaxf(mx0, __shfl_xor_sync(0xffffffff, mx0, 2));
            mx1 = fmaxf(mx1, __shfl_xor_sync(0xffffffff, mx1, 1));
            mx1 = fmaxf(mx1, __shfl_xor_sync(0xffffffff, mx1, 2));

            float mn0 = fmaxf(m0, mx0), mn1 = fmaxf(m1, mx1);
            float f0 = __expf(m0 - mn0), f1 = __expf(m1 - mn1);
            m0 = mn0; m1 = mn1;

            float sum0 = 0.f, sum1 = 0.f;
#pragma unroll
            for (int ni = 0; ni < 8; ni++) {
                s[ni][0] = __expf(s[ni][0] - mn0);
                s[ni][1] = __expf(s[ni][1] - mn0);
                s[ni][2] = __expf(s[ni][2] - mn1);
                s[ni][3] = __expf(s[ni][3] - mn1);
                sum0 += s[ni][0] + s[ni][1];
                sum1 += s[ni][2] + s[ni][3];
            }
            sum0 += __shfl_xor_sync(0xffffffff, sum0, 1);
            sum0 += __shfl_xor_sync(0xffffffff, sum0, 2);
            sum1 += __shfl_xor_sync(0xffffffff, sum1, 1);
            sum1 += __shfl_xor_sync(0xffffffff, sum1, 2);
            l0 = l0 * f0 + sum0;
            l1 = l1 * f1 + sum1;

#pragma unroll
            for (int nd = 0; nd < 8; nd++) {
                o[nd][0] *= f0; o[nd][1] *= f0;
                o[nd][2] *= f1; o[nd][3] *= f1;
            }

            uint32_t pfh[4][4], pfl[4][4];
#pragma unroll
            for (int j = 0; j < 4; j++) {
                float p00 = s[2 * j][0],     p01 = s[2 * j][1];
                float p10 = s[2 * j][2],     p11 = s[2 * j][3];
                float p20 = s[2 * j + 1][0], p21 = s[2 * j + 1][1];
                float p30 = s[2 * j + 1][2], p31 = s[2 * j + 1][3];
                pfh[j][0] = pack_bf16(p00, p01);
                pfh[j][1] = pack_bf16(p10, p11);
                pfh[j][2] = pack_bf16(p20, p21);
                pfh[j][3] = pack_bf16(p30, p31);
                __nv_bfloat162* hp;
                hp = (__nv_bfloat162*)&pfh[j][0];
                pfl[j][0] = pack_bf16(p00 - __bfloat162float(hp->x), p01 - __bfloat162float(hp->y));
                hp = (__nv_bfloat162*)&pfh[j][1];
                pfl[j][1] = pack_bf16(p10 - __bfloat162float(hp->x), p11 - __bfloat162float(hp->y));
                hp = (__nv_bfloat162*)&pfh[j][2];
                pfl[j][2] = pack_bf16(p20 - __bfloat162float(hp->x), p21 - __bfloat162float(hp->y));
                hp = (__nv_bfloat162*)&pfh[j][3];
                pfl[j][3] = pack_bf16(p30 - __bfloat162float(hp->x), p31 - __bfloat162float(hp->y));
            }

#pragma unroll
            for (int j = 0; j < 4; j++) {
#pragma unroll
                for (int dp = 0; dp < 4; dp++) {
                    uint32_t ad = ((j * 16 + kq * 8 + l8) * LDK + dp * 16 + half_ * 8) * 2;
                    uint32_t th[4], tl[4];
                    ldsm4t(th, sVh_ + ad);
                    ldsm4t(tl, sVl_ + ad);
                    uint32_t b0a[2] = {th[0], th[2]}, b1a[2] = {th[1], th[3]};
                    uint32_t b0b[2] = {tl[0], tl[2]}, b1b[2] = {tl[1], tl[3]};
                    mma_bf16(o[2 * dp], pfh[j], b0a);
                    mma_bf16(o[2 * dp], pfh[j], b0b);
                    mma_bf16(o[2 * dp], pfl[j], b0a);
                    mma_bf16(o[2 * dp + 1], pfh[j], b1a);
                    mma_bf16(o[2 * dp + 1], pfh[j], b1b);
                    mma_bf16(o[2 * dp + 1], pfl[j], b1a);
                }
            }
        }
    }

    // --- normalize; write fp16 hi + fp8 + fp8-lo context (O-proj A-side) ---
    float li0 = 1.0f / l0, li1 = 1.0f / l1;
    const size_t r0 = (size_t)(b * S_ + row_base + g) * HID_ + h * HD_;
    const size_t r1 = (size_t)(b * S_ + row_base + g + 8) * HID_ + h * HD_;
#pragma unroll
    for (int nd = 0; nd < 8; nd++) {
        int c = nd * 8 + 2 * t;
        float v0 = o[nd][0] * li0, v1 = o[nd][1] * li0;
        float v2 = o[nd][2] * li1, v3 = o[nd][3] * li1;
        __half2 h01 = __floats2half2_rn(v0, v1);
        __half2 h23 = __floats2half2_rn(v2, v3);
        *(uint32_t*)&c16[r0 + c] = *(uint32_t*)&h01;
        *(uint32_t*)&c16[r1 + c] = *(uint32_t*)&h23;
        cq[r0 + c]     = to_e4m3(v0);
        cq[r0 + c + 1] = to_e4m3(v1);
        cq[r1 + c]     = to_e4m3(v2);
        cq[r1 + c + 1] = to_e4m3(v3);
        clq[r0 + c]     = to_e4m3((v0 - __half2float(__low2half(h01))) * 4096.0f);
        clq[r0 + c + 1] = to_e4m3((v1 - __half2float(__high2half(h01))) * 4096.0f);
        clq[r1 + c]     = to_e4m3((v2 - __half2float(__low2half(h23))) * 4096.0f);
        clq[r1 + c + 1] = to_e4m3((v3 - __half2float(__high2half(h23))) * 4096.0f);
    }
}

// ---------------------------------------------------------------------------
// Launch
// ---------------------------------------------------------------------------
extern "C" void kernel_launch(void* const* d_in, const int* in_sizes, int n_in,
                              void* d_out, int out_size)
{
    const float* hidden = (const float*)d_in[0];
    const float* wq = (const float*)d_in[2];
    const float* wk = (const float*)d_in[3];
    const float* wv = (const float*)d_in[4];
    const float* wo = (const float*)d_in[5];
    float* out = (float*)d_out;

    float* qkv;
    cudaGetSymbolAddress((void**)&qkv, g_QKV);

    __half *h16, *wc16, *wo16, *c16;
    uint8_t *hq, *hlq, *wcq, *wclq, *woq, *wolq, *cq, *clq;
    __nv_bfloat16 *qh, *ql, *kh, *kl, *vh, *vl;
    cudaGetSymbolAddress((void**)&h16, g_h16);
    cudaGetSymbolAddress((void**)&hq, g_hq);     cudaGetSymbolAddress((void**)&hlq, g_hlq);
    cudaGetSymbolAddress((void**)&wc16, g_wc16);
    cudaGetSymbolAddress((void**)&wcq, g_wcq);   cudaGetSymbolAddress((void**)&wclq, g_wclq);
    cudaGetSymbolAddress((void**)&wo16, g_wo16);
    cudaGetSymbolAddress((void**)&woq, g_woq);   cudaGetSymbolAddress((void**)&wolq, g_wolq);
    cudaGetSymbolAddress((void**)&c16, g_c16);
    cudaGetSymbolAddress((void**)&cq, g_cq);     cudaGetSymbolAddress((void**)&clq, g_clq);
    cudaGetSymbolAddress((void**)&qh, g_qh);     cudaGetSymbolAddress((void**)&ql, g_ql);
    cudaGetSymbolAddress((void**)&kh, g_kh);     cudaGetSymbolAddress((void**)&kl, g_kl);
    cudaGetSymbolAddress((void**)&vh, g_vh);     cudaGetSymbolAddress((void**)&vl, g_vl);

    const int GEMM_DYN = GSTG * STGB;            // 202752 B
    const int FLASH_DYN = FSTG * 4 * KVT * 2;    // 110592 B
    cudaFuncSetAttribute(gemm_mma, cudaFuncAttributeMaxDynamicSharedMemorySize, GEMM_DYN);
    cudaFuncSetAttribute(flash_mma, cudaFuncAttributeMaxDynamicSharedMemorySize, FLASH_DYN);

    // Splits
    {
        int n1 = M_TOT * HID_;
        split_a<<<(n1 + 255) / 256, 256>>>(hidden, h16, hq, hlq, n1);
        int n2 = HID_ * HID_;
        split_b<<<(n2 + 255) / 256, 256>>>(wq, wc16, wcq, wclq, n2);
        int n3 = NKVD * HID_;
        split_b<<<(n3 + 255) / 256, 256>>>(wk, wc16 + (size_t)HID_ * HID_,
                                           wcq + (size_t)HID_ * HID_, wclq + (size_t)HID_ * HID_, n3);
        split_b<<<(n3 + 255) / 256, 256>>>(wv, wc16 + (size_t)(HID_ + NKVD) * HID_,
                                           wcq + (size_t)(HID_ + NKVD) * HID_,
                                           wclq + (size_t)(HID_ + NKVD) * HID_, n3);
        split_b<<<(n2 + 255) / 256, 256>>>(wo, wo16, woq, wolq, n2);
    }

    rope_table_kernel<<<(S_ * 32) / 256, 256>>>();

    // Fused QKV projection (fp16 + fp8-cross GEMM)
    gemm_mma<<<dim3(NQKV / BN, M_TOT / BM), 512, GEMM_DYN>>>(
        h16, hq, hlq, wc16, wcq, wclq, qkv, M_TOT, NQKV, HID_);

    // RoPE + split to bf16 (attention operands)
    rope_split_kernel<<<(M_TOT * NH_ * 32) / 256, 256>>>(qkv, qh, ql, NH_, 0);
    rope_split_kernel<<<(M_TOT * NKV_ * 32) / 256, 256>>>(qkv, kh, kl, NKV_, HID_);
    split_v_kernel<<<(M_TOT * NKVD) / 256, 256>>>(qkv, vh, vl);

    // Tensor-core flash attention (writes fp16/fp8 context)
    flash_mma<<<dim3(S_ / 128, NH_, B_), 256, FLASH_DYN>>>(qh, ql, kh, kl, vh, vl, c16, cq, clq);

    // O projection
    gemm_mma<<<dim3(HID_ / BN, M_TOT / BM), 512, GEMM_DYN>>>(
        c16, cq, clq, wo16, woq, wolq, out, M_TOT, HID_, HID_);
}